// round 7
// baseline (speedup 1.0000x reference)
#include <cuda_runtime.h>
#include <cuda_fp16.h>
#include <cstdint>

#define BB   2
#define CFI  32
#define HH   192
#define WWD  192
#define NN   (HH*WWD)        // 36864
#define NUMK 16
#define CT   67
#define EPSL 1e-5f
#define TS   256
#define NT   (NN/TS)         // 144

// ---------------- scratch (static device globals; no allocation) ----------------
__device__ float g_P[BB*NN*CFI];        // [b][n][c]
__device__ float g_Q[BB*NN*CFI];        // [b][n][c]
__device__ float g_U[BB*NUMK*NN];
__device__ float g_Om[BB*NUMK*NN];

__device__ float g_WPQ[64*32];
__device__ float g_w1p[32], g_w1a[32], g_w1b[32], g_t1[32];
// packed f16x2 weights per layer: [k2][32] uint32, hi at [0,512), lo at [512,1024)
// wpack[k2][n] = {f16(W[n][2k2]*inv), f16(W[n][2k2+1]*inv)}
__device__ unsigned g_W2p[1024];
__device__ unsigned g_W3p[1024];
__device__ unsigned g_W4p[1024];
__device__ float g_t2[32], g_t3[32], g_t4[32];
__device__ float g_wcA[32], g_wcB[32], g_wcC[32];
__device__ float g_bcv[3];
__device__ int   g_args64;
// gelu lookup table: 2048 segments on [-8,8], (slope, intercept) pairs
__device__ float g_tab[4096];

__device__ __forceinline__ float frcp(float x) { float y; asm("rcp.approx.f32 %0, %1;" : "=f"(y) : "f"(x)); return y; }
__device__ __forceinline__ float fex2(float x) { float y; asm("ex2.approx.f32 %0, %1;" : "=f"(y) : "f"(x)); return y; }

// m16n8k16 fp16 MMA, row.col, fp32 accumulate in-place
__device__ __forceinline__ void mma16(float* d, unsigned a0, unsigned a1, unsigned a2, unsigned a3,
                                      unsigned b0, unsigned b1) {
    asm volatile(
        "mma.sync.aligned.m16n8k16.row.col.f32.f16.f16.f32 "
        "{%0,%1,%2,%3}, {%4,%5,%6,%7}, {%8,%9}, {%0,%1,%2,%3};"
        : "+f"(d[0]), "+f"(d[1]), "+f"(d[2]), "+f"(d[3])
        : "r"(a0), "r"(a1), "r"(a2), "r"(a3), "r"(b0), "r"(b1));
}

// table gelu: linear segments, g = slope*x + intercept
__device__ __forceinline__ float gelu_t(float x, const float* __restrict__ tab) {
    float u = fmaf(x, 128.0f, 1024.0f);
    u = fminf(fmaxf(u, 0.0f), 2047.0f);
    int i = (int)u;
    float2 si = *(const float2*)(tab + 2*i);
    return fmaf(si.x, x, si.y);
}

// ---------------- kernel 1: fold BN, pack fp16 weights, build gelu table ----------------
__global__ void prep_kernel(
    const float* __restrict__ W1, const float* __restrict__ g1, const float* __restrict__ b1,
    const float* __restrict__ m1, const float* __restrict__ v1,
    const float* __restrict__ W2, const float* __restrict__ g2, const float* __restrict__ b2,
    const float* __restrict__ m2, const float* __restrict__ v2,
    const float* __restrict__ W3, const float* __restrict__ g3, const float* __restrict__ b3,
    const float* __restrict__ m3, const float* __restrict__ v3,
    const float* __restrict__ W4, const float* __restrict__ g4, const float* __restrict__ b4,
    const float* __restrict__ m4, const float* __restrict__ v4,
    const float* __restrict__ Wc, const float* __restrict__ bc,
    const int*   __restrict__ args_i32)
{
    __shared__ float inv1[32], inv2[32], inv3[32], inv4[32];
    int t = threadIdx.x;
    if (t < 32) {
        float i1 = g1[t]*rsqrtf(v1[t]+EPSL); inv1[t]=i1; g_t1[t]=b1[t]-m1[t]*i1;
        float i2 = g2[t]*rsqrtf(v2[t]+EPSL); inv2[t]=i2; g_t2[t]=b2[t]-m2[t]*i2;
        float i3 = g3[t]*rsqrtf(v3[t]+EPSL); inv3[t]=i3; g_t3[t]=b3[t]-m3[t]*i3;
        float i4 = g4[t]*rsqrtf(v4[t]+EPSL); inv4[t]=i4; g_t4[t]=b4[t]-m4[t]*i4;
        g_wcA[t]=Wc[t]; g_wcB[t]=Wc[32+t]; g_wcC[t]=Wc[64+t];
        g_w1p[t]=W1[t*CT+64]*i1; g_w1a[t]=W1[t*CT+65]*i1; g_w1b[t]=W1[t*CT+66]*i1;
    }
    if (t < 3) g_bcv[t] = bc[t];
    if (t == 0) {
        int all_zero = 1;
        for (int i = 0; i < 128; i++) if (args_i32[2*i+1] != 0) { all_zero = 0; break; }
        g_args64 = all_zero;
    }
    __syncthreads();
    for (int idx = t; idx < 2048; idx += blockDim.x) {
        int r = idx >> 5, i = idx & 31;
        g_WPQ[idx] = (r < 32) ? W1[r*CT + i] * inv1[r]
                              : W1[(r-32)*CT + 32 + i] * inv1[r-32];
    }
    // packed fp16 hi + residual-lo weights: idx = k2*32 + n
    for (int idx = t; idx < 512; idx += blockDim.x) {
        int k2 = idx >> 5, n = idx & 31;
        float w0, w1;
        __half2 ph, pl;
        w0 = W2[n*32 + 2*k2]*inv2[n]; w1 = W2[n*32 + 2*k2 + 1]*inv2[n];
        ph = __floats2half2_rn(w0, w1);
        pl = __floats2half2_rn(w0 - __low2float(ph), w1 - __high2float(ph));
        g_W2p[idx] = *(unsigned*)&ph; g_W2p[512+idx] = *(unsigned*)&pl;
        w0 = W3[n*32 + 2*k2]*inv3[n]; w1 = W3[n*32 + 2*k2 + 1]*inv3[n];
        ph = __floats2half2_rn(w0, w1);
        pl = __floats2half2_rn(w0 - __low2float(ph), w1 - __high2float(ph));
        g_W3p[idx] = *(unsigned*)&ph; g_W3p[512+idx] = *(unsigned*)&pl;
        w0 = W4[n*32 + 2*k2]*inv4[n]; w1 = W4[n*32 + 2*k2 + 1]*inv4[n];
        ph = __floats2half2_rn(w0, w1);
        pl = __floats2half2_rn(w0 - __low2float(ph), w1 - __high2float(ph));
        g_W4p[idx] = *(unsigned*)&ph; g_W4p[512+idx] = *(unsigned*)&pl;
    }
    // gelu table: segment i covers [x0, x0+1/128), store slope + intercept
    for (int i = t; i < 2048; i += blockDim.x) {
        float x0 = -8.0f + i * (1.0f/128.0f);
        float x1 = x0 + (1.0f/128.0f);
        float g0 = 0.5f * x0 * (1.0f + erff(x0 * 0.70710678118654752f));
        float gg1 = 0.5f * x1 * (1.0f + erff(x1 * 0.70710678118654752f));
        float slope = (gg1 - g0) * 128.0f;
        g_tab[2*i]   = slope;
        g_tab[2*i+1] = fmaf(-slope, x0, g0);
    }
}

// ---------------- kernel 2: P/Q = folded-W1 @ If, written [b][n][c] ----------------
__global__ void pq_kernel(const float* __restrict__ If)
{
    __shared__ float wf[2048];
    __shared__ float tb[256*33];
    int tid  = threadIdx.x;
    int b    = blockIdx.x / NT;
    int tile = blockIdx.x % NT;
    int n0   = tile * 256;

    for (int idx = tid; idx < 2048; idx += 256) wf[idx] = g_WPQ[idx];

    int n = n0 + tid;
    float x[32];
    #pragma unroll
    for (int i = 0; i < 32; i++) x[i] = If[((size_t)b*32 + i)*NN + n];
    __syncthreads();

    size_t base = ((size_t)b*NN + n0) * 32;

    #pragma unroll
    for (int c = 0; c < 32; c++) {
        float acc = 0.f;
        #pragma unroll
        for (int i = 0; i < 32; i += 4) {
            float4 w = *(const float4*)&wf[c*32 + i];
            acc += w.x*x[i] + w.y*x[i+1] + w.z*x[i+2] + w.w*x[i+3];
        }
        tb[tid*33 + c] = acc;
    }
    __syncthreads();
    for (int idx = tid; idx < 8192; idx += 256)
        g_P[base + idx] = tb[(idx >> 5)*33 + (idx & 31)];
    __syncthreads();

    #pragma unroll
    for (int c = 0; c < 32; c++) {
        float acc = 0.f;
        #pragma unroll
        for (int i = 0; i < 32; i += 4) {
            float4 w = *(const float4*)&wf[(32+c)*32 + i];
            acc += w.x*x[i] + w.y*x[i+1] + w.z*x[i+2] + w.w*x[i+3];
        }
        tb[tid*33 + c] = acc;
    }
    __syncthreads();
    for (int idx = tid; idx < 8192; idx += 256)
        g_Q[base + idx] = tb[(idx >> 5)*33 + (idx & 31)];
}

// ---------------- register-resident MLP layer (2-pass fp16 mma, B split) ----------------
// x layout: x[mt*16 + nt*4 + e], channel = 8*nt + 2*tg + (e&1),
//           sample row = 32*warp + 16*mt + g + 8*(e>>1)
template<bool ADD>
__device__ __forceinline__ void layer_reg(
    const float* xin, float* xout,
    const unsigned* __restrict__ wp, const float* __restrict__ bias,
    const float* resid, int g, int tg, const float* __restrict__ tab)
{
    // pack activations to single fp16 (no split)
    unsigned ah[16];
    #pragma unroll
    for (int mt = 0; mt < 2; mt++)
    #pragma unroll
    for (int nt = 0; nt < 4; nt++) {
        int base = mt*16 + nt*4;
        #pragma unroll
        for (int hh = 0; hh < 2; hh++) {
            __half2 p = __floats2half2_rn(xin[base + 2*hh], xin[base + 2*hh + 1]);
            ah[(mt*4 + nt)*2 + hh] = *(unsigned*)&p;
        }
    }
    // init accumulators with bias
    float d[32];
    #pragma unroll
    for (int nt = 0; nt < 4; nt++) {
        float2 bv = __ldg((const float2*)bias + 4*nt + tg);
        #pragma unroll
        for (int mt = 0; mt < 2; mt++) {
            d[mt*16 + nt*4 + 0] = bv.x; d[mt*16 + nt*4 + 1] = bv.y;
            d[mt*16 + nt*4 + 2] = bv.x; d[mt*16 + nt*4 + 3] = bv.y;
        }
    }
    // mma mainloop: 2 k-steps x 4 n-tiles x 2 m-tiles x 2 passes (Bh, Bl)
    #pragma unroll
    for (int ks = 0; ks < 2; ks++) {
        #pragma unroll
        for (int nt = 0; nt < 4; nt++) {
            unsigned bh0 = __ldg(wp +        (ks*8 + tg    )*32 + 8*nt + g);
            unsigned bh1 = __ldg(wp +        (ks*8 + tg + 4)*32 + 8*nt + g);
            unsigned bl0 = __ldg(wp + 512 +  (ks*8 + tg    )*32 + 8*nt + g);
            unsigned bl1 = __ldg(wp + 512 +  (ks*8 + tg + 4)*32 + 8*nt + g);
            #pragma unroll
            for (int mt = 0; mt < 2; mt++) {
                int ia  = (mt*4 + 2*ks    )*2;
                int ia2 = (mt*4 + 2*ks + 1)*2;
                float* dd = d + mt*16 + nt*4;
                mma16(dd, ah[ia], ah[ia+1], ah[ia2], ah[ia2+1], bh0, bh1);
                mma16(dd, ah[ia], ah[ia+1], ah[ia2], ah[ia2+1], bl0, bl1);
            }
        }
    }
    #pragma unroll
    for (int i = 0; i < 32; i++) {
        float v = d[i];
        if (ADD) v += resid[i];
        xout[i] = gelu_t(v, tab);
    }
}

// ---------------- kernel 3: main fused MLP, fully register-resident ----------------
__global__ void __launch_bounds__(256) main_kernel(
    const float* __restrict__ Pf,
    const float* __restrict__ Of,
    const void*  __restrict__ args)
{
    __shared__ float stab[4096];        // gelu table: 16KB
    int tid = threadIdx.x;
    for (int idx = tid; idx < 4096; idx += 256) stab[idx] = g_tab[idx];
    __syncthreads();

    int bk   = blockIdx.x / NT;
    int tile = blockIdx.x % NT;
    int b = bk / NUMK, k = bk % NUMK;
    int n0 = tile * TS;
    int w = tid >> 5, lane = tid & 31;
    int g = lane >> 2, tg = lane & 3;

    float xa[32], xb[32];
    float pfs[4];

    // stage 1: h1 in D-frag register layout
    {
        float2 w1p2[4], w1a2[4], w1b2[4], t12[4];
        #pragma unroll
        for (int q = 0; q < 4; q++) {
            w1p2[q] = __ldg((const float2*)g_w1p + 4*q + tg);
            w1a2[q] = __ldg((const float2*)g_w1a + 4*q + tg);
            w1b2[q] = __ldg((const float2*)g_w1b + 4*q + tg);
            t12[q]  = __ldg((const float2*)g_t1  + 4*q + tg);
        }
        const float* of0p = Of + ((size_t)(b*2+0)*NUMK + k)*NN;
        const float* of1p = Of + ((size_t)(b*2+1)*NUMK + k)*NN;
        int use64 = g_args64;
        #pragma unroll
        for (int mt = 0; mt < 2; mt++)
        #pragma unroll
        for (int hh = 0; hh < 2; hh++) {
            int s = 32*w + 16*mt + 8*hh + g;
            int n = n0 + s;
            size_t ai = ((size_t)(b*NUMK + k))*NN + n;
            int j;
            if (use64) j = (int)__ldg((const long long*)args + ai);
            else       j = __ldg((const int*)args + ai);
            float pf = __ldg(Pf + (size_t)b*NN + j);
            pfs[mt*2 + hh] = pf;
            float o0 = __ldg(of0p + n);
            float o1 = __ldg(of1p + n);
            const float2* P2 = (const float2*)g_P + (size_t)(b*NN + n)*16 + tg;
            const float2* Q2 = (const float2*)g_Q + (size_t)(b*NN + j)*16 + tg;
            #pragma unroll
            for (int q = 0; q < 4; q++) {
                float2 p  = __ldg(P2 + 4*q);
                float2 qv = __ldg(Q2 + 4*q);
                float z0 = p.x + qv.x + w1p2[q].x*pf + w1a2[q].x*o0 + w1b2[q].x*o1 + t12[q].x;
                float z1 = p.y + qv.y + w1p2[q].y*pf + w1a2[q].y*o0 + w1b2[q].y*o1 + t12[q].y;
                xa[mt*16 + q*4 + 2*hh]     = gelu_t(z0, stab);
                xa[mt*16 + q*4 + 2*hh + 1] = gelu_t(z1, stab);
            }
        }
    }

    layer_reg<false>(xa, xb, g_W2p, g_t2, nullptr, g, tg, stab);   // h2 = xb
    layer_reg<false>(xb, xa, g_W3p, g_t3, nullptr, g, tg, stab);   // l3 = xa
    layer_reg<true >(xa, xa, g_W4p, g_t4, xb,      g, tg, stab);   // XF = gelu(h2 + bn4(W4 l3))

    // head: 3x32 dot per sample, reduce across the 4 tg-lanes of each sample
    {
        float2 wA2[4], wB2[4], wC2[4];
        #pragma unroll
        for (int nt = 0; nt < 4; nt++) {
            wA2[nt] = __ldg((const float2*)g_wcA + 4*nt + tg);
            wB2[nt] = __ldg((const float2*)g_wcB + 4*nt + tg);
            wC2[nt] = __ldg((const float2*)g_wcC + 4*nt + tg);
        }
        float bc0 = g_bcv[0], bc1 = g_bcv[1], bc2 = g_bcv[2];
        size_t obase = ((size_t)(b*NUMK + k))*NN + n0;
        #pragma unroll
        for (int mt = 0; mt < 2; mt++)
        #pragma unroll
        for (int hh = 0; hh < 2; hh++) {
            float a = 0.f, be = 0.f, om = 0.f;
            #pragma unroll
            for (int nt = 0; nt < 4; nt++) {
                float x0 = xa[mt*16 + nt*4 + 2*hh];
                float x1 = xa[mt*16 + nt*4 + 2*hh + 1];
                a  += wA2[nt].x*x0 + wA2[nt].y*x1;
                be += wB2[nt].x*x0 + wB2[nt].y*x1;
                om += wC2[nt].x*x0 + wC2[nt].y*x1;
            }
            a  += __shfl_xor_sync(0xffffffffu, a, 1);
            a  += __shfl_xor_sync(0xffffffffu, a, 2);
            be += __shfl_xor_sync(0xffffffffu, be, 1);
            be += __shfl_xor_sync(0xffffffffu, be, 2);
            om += __shfl_xor_sync(0xffffffffu, om, 1);
            om += __shfl_xor_sync(0xffffffffu, om, 2);
            if (tg == 0) {
                int s = 32*w + 16*mt + 8*hh + g;
                float U = (a + bc0 + 1.0f)*pfs[mt*2 + hh] + (be + bc1);
                g_U[obase + s]  = U;
                g_Om[obase + s] = om + bc2;
            }
        }
    }
}

// ---------------- kernel 4: softmax over NUM + weighted sum ----------------
__global__ void epi_kernel(float* __restrict__ out)
{
    int gid = blockIdx.x * blockDim.x + threadIdx.x;
    if (gid >= BB*NN) return;
    int b = gid / NN, n = gid % NN;
    size_t base = (size_t)b*NUMK*NN + n;
    float om[NUMK];
    float m = -3.4e38f;
    #pragma unroll
    for (int k = 0; k < NUMK; k++) {
        om[k] = g_Om[base + (size_t)k*NN];
        m = fmaxf(m, om[k]);
    }
    float num = 0.f, den = 0.f;
    #pragma unroll
    for (int k = 0; k < NUMK; k++) {
        float e = fex2((om[k] - m) * 1.4426950408889634f);
        den += e;
        num += e * g_U[base + (size_t)k*NN];
    }
    out[gid] = num * frcp(den);
}

// ---------------- launch ----------------
extern "C" void kernel_launch(void* const* d_in, const int* in_sizes, int n_in,
                              void* d_out, int out_size)
{
    const float* If = (const float*)d_in[0];
    const float* Pf = (const float*)d_in[1];
    const float* Of = (const float*)d_in[2];
    const void*  args = d_in[3];
    const float* W1 = (const float*)d_in[4];
    const float* g1 = (const float*)d_in[5];
    const float* b1 = (const float*)d_in[6];
    const float* m1 = (const float*)d_in[7];
    const float* v1 = (const float*)d_in[8];
    const float* W2 = (const float*)d_in[9];
    const float* g2 = (const float*)d_in[10];
    const float* b2 = (const float*)d_in[11];
    const float* m2 = (const float*)d_in[12];
    const float* v2 = (const float*)d_in[13];
    const float* W3 = (const float*)d_in[14];
    const float* g3 = (const float*)d_in[15];
    const float* b3 = (const float*)d_in[16];
    const float* m3 = (const float*)d_in[17];
    const float* v3 = (const float*)d_in[18];
    const float* W4 = (const float*)d_in[19];
    const float* g4 = (const float*)d_in[20];
    const float* b4 = (const float*)d_in[21];
    const float* m4 = (const float*)d_in[22];
    const float* v4 = (const float*)d_in[23];
    const float* Wc = (const float*)d_in[24];
    const float* bc = (const float*)d_in[25];

    prep_kernel<<<1, 256>>>(W1, g1, b1, m1, v1,
                            W2, g2, b2, m2, v2,
                            W3, g3, b3, m3, v3,
                            W4, g4, b4, m4, v4,
                            Wc, bc, (const int*)args);

    pq_kernel<<<BB*NT, 256>>>(If);

    main_kernel<<<BB*NUMK*NT, 256>>>(Pf, Of, args);

    epi_kernel<<<(BB*NN + 255)/256, 256>>>((float*)d_out);
}

// round 8
// speedup vs baseline: 1.4101x; 1.4101x over previous
#include <cuda_runtime.h>
#include <cuda_fp16.h>
#include <cstdint>

#define BB   2
#define CFI  32
#define HH   192
#define WWD  192
#define NN   (HH*WWD)        // 36864
#define NUMK 16
#define CT   67
#define EPSL 1e-5f
#define TS   256
#define NT   (NN/TS)         // 144

// ---------------- scratch (static device globals; no allocation) ----------------
__device__ float g_P[BB*NN*CFI];        // [b][n][c]
__device__ float g_Q[BB*NN*CFI];        // [b][n][c]
__device__ float g_U[BB*NUMK*NN];
__device__ float g_Om[BB*NUMK*NN];

__device__ float g_WPQ[64*32];
__device__ float g_w1p[32], g_w1a[32], g_w1b[32], g_t1[32];
// packed f16x2 weights per layer: [k2][32] uint32, hi at [0,512), lo at [512,1024)
__device__ unsigned g_W2p[1024];
__device__ unsigned g_W3p[1024];
__device__ unsigned g_W4p[1024];
__device__ float g_t2[32], g_t3[32], g_t4[32];
__device__ float g_wcA[32], g_wcB[32], g_wcC[32];
__device__ float g_bcv[3];
__device__ int   g_args64;

__device__ __forceinline__ float frcp(float x) { float y; asm("rcp.approx.f32 %0, %1;" : "=f"(y) : "f"(x)); return y; }
__device__ __forceinline__ float fex2(float x) { float y; asm("ex2.approx.f32 %0, %1;" : "=f"(y) : "f"(x)); return y; }

// m16n8k16 fp16 MMA, row.col, fp32 accumulate in-place
__device__ __forceinline__ void mma16(float* d, unsigned a0, unsigned a1, unsigned a2, unsigned a3,
                                      unsigned b0, unsigned b1) {
    asm volatile(
        "mma.sync.aligned.m16n8k16.row.col.f32.f16.f16.f32 "
        "{%0,%1,%2,%3}, {%4,%5,%6,%7}, {%8,%9}, {%0,%1,%2,%3};"
        : "+f"(d[0]), "+f"(d[1]), "+f"(d[2]), "+f"(d[3])
        : "r"(a0), "r"(a1), "r"(a2), "r"(a3), "r"(b0), "r"(b1));
}

// fast gelu: 0.5*(x + |x|*erf(|x|/sqrt2)), erf via A&S 7.1.26 (|eps|<=1.5e-7)
__device__ __forceinline__ float gelu_f(float x) {
    float ax = fabsf(x);
    float z  = ax * 0.70710678118654752f;
    float t  = frcp(fmaf(z, 0.3275911f, 1.0f));
    float e  = fex2(z * z * -1.4426950408889634f);
    float h  = fmaf(1.061405429f, t, -1.453152027f);
    h = fmaf(h, t, 1.421413741f);
    h = fmaf(h, t, -0.284496736f);
    h = fmaf(h, t, 0.254829592f);
    h = h * t;
    float E = fmaf(-h, e, 1.0f);
    return 0.5f * fmaf(ax, E, x);
}

// ---------------- kernel 1: fold BN, pack fp16 weights, detect args dtype ----------------
__global__ void prep_kernel(
    const float* __restrict__ W1, const float* __restrict__ g1, const float* __restrict__ b1,
    const float* __restrict__ m1, const float* __restrict__ v1,
    const float* __restrict__ W2, const float* __restrict__ g2, const float* __restrict__ b2,
    const float* __restrict__ m2, const float* __restrict__ v2,
    const float* __restrict__ W3, const float* __restrict__ g3, const float* __restrict__ b3,
    const float* __restrict__ m3, const float* __restrict__ v3,
    const float* __restrict__ W4, const float* __restrict__ g4, const float* __restrict__ b4,
    const float* __restrict__ m4, const float* __restrict__ v4,
    const float* __restrict__ Wc, const float* __restrict__ bc,
    const int*   __restrict__ args_i32)
{
    __shared__ float inv1[32], inv2[32], inv3[32], inv4[32];
    int t = threadIdx.x;
    if (t < 32) {
        float i1 = g1[t]*rsqrtf(v1[t]+EPSL); inv1[t]=i1; g_t1[t]=b1[t]-m1[t]*i1;
        float i2 = g2[t]*rsqrtf(v2[t]+EPSL); inv2[t]=i2; g_t2[t]=b2[t]-m2[t]*i2;
        float i3 = g3[t]*rsqrtf(v3[t]+EPSL); inv3[t]=i3; g_t3[t]=b3[t]-m3[t]*i3;
        float i4 = g4[t]*rsqrtf(v4[t]+EPSL); inv4[t]=i4; g_t4[t]=b4[t]-m4[t]*i4;
        g_wcA[t]=Wc[t]; g_wcB[t]=Wc[32+t]; g_wcC[t]=Wc[64+t];
        g_w1p[t]=W1[t*CT+64]*i1; g_w1a[t]=W1[t*CT+65]*i1; g_w1b[t]=W1[t*CT+66]*i1;
    }
    if (t < 3) g_bcv[t] = bc[t];
    if (t == 0) {
        int all_zero = 1;
        for (int i = 0; i < 128; i++) if (args_i32[2*i+1] != 0) { all_zero = 0; break; }
        g_args64 = all_zero;
    }
    __syncthreads();
    for (int idx = t; idx < 2048; idx += blockDim.x) {
        int r = idx >> 5, i = idx & 31;
        g_WPQ[idx] = (r < 32) ? W1[r*CT + i] * inv1[r]
                              : W1[(r-32)*CT + 32 + i] * inv1[r-32];
    }
    // packed fp16 hi + residual-lo weights: idx = k2*32 + n
    for (int idx = t; idx < 512; idx += blockDim.x) {
        int k2 = idx >> 5, n = idx & 31;
        float w0, w1;
        __half2 ph, pl;
        w0 = W2[n*32 + 2*k2]*inv2[n]; w1 = W2[n*32 + 2*k2 + 1]*inv2[n];
        ph = __floats2half2_rn(w0, w1);
        pl = __floats2half2_rn(w0 - __low2float(ph), w1 - __high2float(ph));
        g_W2p[idx] = *(unsigned*)&ph; g_W2p[512+idx] = *(unsigned*)&pl;
        w0 = W3[n*32 + 2*k2]*inv3[n]; w1 = W3[n*32 + 2*k2 + 1]*inv3[n];
        ph = __floats2half2_rn(w0, w1);
        pl = __floats2half2_rn(w0 - __low2float(ph), w1 - __high2float(ph));
        g_W3p[idx] = *(unsigned*)&ph; g_W3p[512+idx] = *(unsigned*)&pl;
        w0 = W4[n*32 + 2*k2]*inv4[n]; w1 = W4[n*32 + 2*k2 + 1]*inv4[n];
        ph = __floats2half2_rn(w0, w1);
        pl = __floats2half2_rn(w0 - __low2float(ph), w1 - __high2float(ph));
        g_W4p[idx] = *(unsigned*)&ph; g_W4p[512+idx] = *(unsigned*)&pl;
    }
}

// ---------------- kernel 2: P/Q = folded-W1 @ If, written [b][n][c] ----------------
__global__ void pq_kernel(const float* __restrict__ If)
{
    __shared__ float wf[2048];
    __shared__ float tb[256*33];
    int tid  = threadIdx.x;
    int b    = blockIdx.x / NT;
    int tile = blockIdx.x % NT;
    int n0   = tile * 256;

    for (int idx = tid; idx < 2048; idx += 256) wf[idx] = g_WPQ[idx];

    int n = n0 + tid;
    float x[32];
    #pragma unroll
    for (int i = 0; i < 32; i++) x[i] = If[((size_t)b*32 + i)*NN + n];
    __syncthreads();

    size_t base = ((size_t)b*NN + n0) * 32;

    #pragma unroll
    for (int c = 0; c < 32; c++) {
        float acc = 0.f;
        #pragma unroll
        for (int i = 0; i < 32; i += 4) {
            float4 w = *(const float4*)&wf[c*32 + i];
            acc += w.x*x[i] + w.y*x[i+1] + w.z*x[i+2] + w.w*x[i+3];
        }
        tb[tid*33 + c] = acc;
    }
    __syncthreads();
    for (int idx = tid; idx < 8192; idx += 256)
        g_P[base + idx] = tb[(idx >> 5)*33 + (idx & 31)];
    __syncthreads();

    #pragma unroll
    for (int c = 0; c < 32; c++) {
        float acc = 0.f;
        #pragma unroll
        for (int i = 0; i < 32; i += 4) {
            float4 w = *(const float4*)&wf[(32+c)*32 + i];
            acc += w.x*x[i] + w.y*x[i+1] + w.z*x[i+2] + w.w*x[i+3];
        }
        tb[tid*33 + c] = acc;
    }
    __syncthreads();
    for (int idx = tid; idx < 8192; idx += 256)
        g_Q[base + idx] = tb[(idx >> 5)*33 + (idx & 31)];
}

// ---------------- register-resident MLP layer (2-pass fp16 mma, B split) ----------------
// x layout: x[mt*16 + nt*4 + e], channel = 8*nt + 2*tg + (e&1),
//           sample row = 32*warp + 16*mt + g + 8*(e>>1)
template<bool ADD>
__device__ __forceinline__ void layer_reg(
    const float* xin, float* xout,
    const unsigned* __restrict__ wp, const float* __restrict__ bias,
    const float* resid, int g, int tg)
{
    // pack activations to fp16 (no split; B carries the residual precision)
    unsigned ah[16];
    #pragma unroll
    for (int mt = 0; mt < 2; mt++)
    #pragma unroll
    for (int nt = 0; nt < 4; nt++) {
        int base = mt*16 + nt*4;
        #pragma unroll
        for (int hh = 0; hh < 2; hh++) {
            __half2 p = __floats2half2_rn(xin[base + 2*hh], xin[base + 2*hh + 1]);
            ah[(mt*4 + nt)*2 + hh] = *(unsigned*)&p;
        }
    }
    // init accumulators with bias
    float d[32];
    #pragma unroll
    for (int nt = 0; nt < 4; nt++) {
        float2 bv = __ldg((const float2*)bias + 4*nt + tg);
        #pragma unroll
        for (int mt = 0; mt < 2; mt++) {
            d[mt*16 + nt*4 + 0] = bv.x; d[mt*16 + nt*4 + 1] = bv.y;
            d[mt*16 + nt*4 + 2] = bv.x; d[mt*16 + nt*4 + 3] = bv.y;
        }
    }
    // mma mainloop: 2 k-steps x 4 n-tiles x 2 m-tiles x 2 passes (Bh, Bl)
    #pragma unroll
    for (int ks = 0; ks < 2; ks++) {
        #pragma unroll
        for (int nt = 0; nt < 4; nt++) {
            unsigned bh0 = __ldg(wp +        (ks*8 + tg    )*32 + 8*nt + g);
            unsigned bh1 = __ldg(wp +        (ks*8 + tg + 4)*32 + 8*nt + g);
            unsigned bl0 = __ldg(wp + 512 +  (ks*8 + tg    )*32 + 8*nt + g);
            unsigned bl1 = __ldg(wp + 512 +  (ks*8 + tg + 4)*32 + 8*nt + g);
            #pragma unroll
            for (int mt = 0; mt < 2; mt++) {
                int ia  = (mt*4 + 2*ks    )*2;
                int ia2 = (mt*4 + 2*ks + 1)*2;
                float* dd = d + mt*16 + nt*4;
                mma16(dd, ah[ia], ah[ia+1], ah[ia2], ah[ia2+1], bh0, bh1);
                mma16(dd, ah[ia], ah[ia+1], ah[ia2], ah[ia2+1], bl0, bl1);
            }
        }
    }
    #pragma unroll
    for (int i = 0; i < 32; i++) {
        float v = d[i];
        if (ADD) v += resid[i];
        xout[i] = gelu_f(v);
    }
}

// ---------------- kernel 3: main fused MLP, fully register-resident ----------------
__global__ void __launch_bounds__(256) main_kernel(
    const float* __restrict__ Pf,
    const float* __restrict__ Of,
    const void*  __restrict__ args)
{
    int bk   = blockIdx.x / NT;
    int tile = blockIdx.x % NT;
    int b = bk / NUMK, k = bk % NUMK;
    int n0 = tile * TS;
    int tid = threadIdx.x;
    int w = tid >> 5, lane = tid & 31;
    int g = lane >> 2, tg = lane & 3;

    float xa[32], xb[32];
    float pfs[4];

    // stage 1: h1 in D-frag register layout
    {
        float2 w1p2[4], w1a2[4], w1b2[4], t12[4];
        #pragma unroll
        for (int q = 0; q < 4; q++) {
            w1p2[q] = __ldg((const float2*)g_w1p + 4*q + tg);
            w1a2[q] = __ldg((const float2*)g_w1a + 4*q + tg);
            w1b2[q] = __ldg((const float2*)g_w1b + 4*q + tg);
            t12[q]  = __ldg((const float2*)g_t1  + 4*q + tg);
        }
        const float* of0p = Of + ((size_t)(b*2+0)*NUMK + k)*NN;
        const float* of1p = Of + ((size_t)(b*2+1)*NUMK + k)*NN;
        int use64 = g_args64;
        #pragma unroll
        for (int mt = 0; mt < 2; mt++)
        #pragma unroll
        for (int hh = 0; hh < 2; hh++) {
            int s = 32*w + 16*mt + 8*hh + g;
            int n = n0 + s;
            size_t ai = ((size_t)(b*NUMK + k))*NN + n;
            int j;
            if (use64) j = (int)__ldg((const long long*)args + ai);
            else       j = __ldg((const int*)args + ai);
            float pf = __ldg(Pf + (size_t)b*NN + j);
            pfs[mt*2 + hh] = pf;
            float o0 = __ldg(of0p + n);
            float o1 = __ldg(of1p + n);
            const float2* P2 = (const float2*)g_P + (size_t)(b*NN + n)*16 + tg;
            const float2* Q2 = (const float2*)g_Q + (size_t)(b*NN + j)*16 + tg;
            #pragma unroll
            for (int q = 0; q < 4; q++) {
                float2 p  = __ldg(P2 + 4*q);
                float2 qv = __ldg(Q2 + 4*q);
                float z0 = p.x + qv.x + w1p2[q].x*pf + w1a2[q].x*o0 + w1b2[q].x*o1 + t12[q].x;
                float z1 = p.y + qv.y + w1p2[q].y*pf + w1a2[q].y*o0 + w1b2[q].y*o1 + t12[q].y;
                xa[mt*16 + q*4 + 2*hh]     = gelu_f(z0);
                xa[mt*16 + q*4 + 2*hh + 1] = gelu_f(z1);
            }
        }
    }

    layer_reg<false>(xa, xb, g_W2p, g_t2, nullptr, g, tg);   // h2 = xb
    layer_reg<false>(xb, xa, g_W3p, g_t3, nullptr, g, tg);   // l3 = xa
    layer_reg<true >(xa, xa, g_W4p, g_t4, xb,      g, tg);   // XF = gelu(h2 + bn4(W4 l3))

    // head: 3x32 dot per sample, reduce across the 4 tg-lanes of each sample
    {
        float2 wA2[4], wB2[4], wC2[4];
        #pragma unroll
        for (int nt = 0; nt < 4; nt++) {
            wA2[nt] = __ldg((const float2*)g_wcA + 4*nt + tg);
            wB2[nt] = __ldg((const float2*)g_wcB + 4*nt + tg);
            wC2[nt] = __ldg((const float2*)g_wcC + 4*nt + tg);
        }
        float bc0 = g_bcv[0], bc1 = g_bcv[1], bc2 = g_bcv[2];
        size_t obase = ((size_t)(b*NUMK + k))*NN + n0;
        #pragma unroll
        for (int mt = 0; mt < 2; mt++)
        #pragma unroll
        for (int hh = 0; hh < 2; hh++) {
            float a = 0.f, be = 0.f, om = 0.f;
            #pragma unroll
            for (int nt = 0; nt < 4; nt++) {
                float x0 = xa[mt*16 + nt*4 + 2*hh];
                float x1 = xa[mt*16 + nt*4 + 2*hh + 1];
                a  += wA2[nt].x*x0 + wA2[nt].y*x1;
                be += wB2[nt].x*x0 + wB2[nt].y*x1;
                om += wC2[nt].x*x0 + wC2[nt].y*x1;
            }
            a  += __shfl_xor_sync(0xffffffffu, a, 1);
            a  += __shfl_xor_sync(0xffffffffu, a, 2);
            be += __shfl_xor_sync(0xffffffffu, be, 1);
            be += __shfl_xor_sync(0xffffffffu, be, 2);
            om += __shfl_xor_sync(0xffffffffu, om, 1);
            om += __shfl_xor_sync(0xffffffffu, om, 2);
            if (tg == 0) {
                int s = 32*w + 16*mt + 8*hh + g;
                float U = (a + bc0 + 1.0f)*pfs[mt*2 + hh] + (be + bc1);
                g_U[obase + s]  = U;
                g_Om[obase + s] = om + bc2;
            }
        }
    }
}

// ---------------- kernel 4: softmax over NUM + weighted sum ----------------
__global__ void epi_kernel(float* __restrict__ out)
{
    int gid = blockIdx.x * blockDim.x + threadIdx.x;
    if (gid >= BB*NN) return;
    int b = gid / NN, n = gid % NN;
    size_t base = (size_t)b*NUMK*NN + n;
    float om[NUMK];
    float m = -3.4e38f;
    #pragma unroll
    for (int k = 0; k < NUMK; k++) {
        om[k] = g_Om[base + (size_t)k*NN];
        m = fmaxf(m, om[k]);
    }
    float num = 0.f, den = 0.f;
    #pragma unroll
    for (int k = 0; k < NUMK; k++) {
        float e = fex2((om[k] - m) * 1.4426950408889634f);
        den += e;
        num += e * g_U[base + (size_t)k*NN];
    }
    out[gid] = num * frcp(den);
}

// ---------------- launch ----------------
extern "C" void kernel_launch(void* const* d_in, const int* in_sizes, int n_in,
                              void* d_out, int out_size)
{
    const float* If = (const float*)d_in[0];
    const float* Pf = (const float*)d_in[1];
    const float* Of = (const float*)d_in[2];
    const void*  args = d_in[3];
    const float* W1 = (const float*)d_in[4];
    const float* g1 = (const float*)d_in[5];
    const float* b1 = (const float*)d_in[6];
    const float* m1 = (const float*)d_in[7];
    const float* v1 = (const float*)d_in[8];
    const float* W2 = (const float*)d_in[9];
    const float* g2 = (const float*)d_in[10];
    const float* b2 = (const float*)d_in[11];
    const float* m2 = (const float*)d_in[12];
    const float* v2 = (const float*)d_in[13];
    const float* W3 = (const float*)d_in[14];
    const float* g3 = (const float*)d_in[15];
    const float* b3 = (const float*)d_in[16];
    const float* m3 = (const float*)d_in[17];
    const float* v3 = (const float*)d_in[18];
    const float* W4 = (const float*)d_in[19];
    const float* g4 = (const float*)d_in[20];
    const float* b4 = (const float*)d_in[21];
    const float* m4 = (const float*)d_in[22];
    const float* v4 = (const float*)d_in[23];
    const float* Wc = (const float*)d_in[24];
    const float* bc = (const float*)d_in[25];

    prep_kernel<<<1, 256>>>(W1, g1, b1, m1, v1,
                            W2, g2, b2, m2, v2,
                            W3, g3, b3, m3, v3,
                            W4, g4, b4, m4, v4,
                            Wc, bc, (const int*)args);

    pq_kernel<<<BB*NT, 256>>>(If);

    main_kernel<<<BB*NUMK*NT, 256>>>(Pf, Of, args);

    epi_kernel<<<(BB*NN + 255)/256, 256>>>((float*)d_out);
}

// round 9
// speedup vs baseline: 1.5783x; 1.1193x over previous
#include <cuda_runtime.h>
#include <cuda_fp16.h>
#include <cstdint>

#define BB   2
#define CFI  32
#define HH   192
#define WWD  192
#define NN   (HH*WWD)        // 36864
#define NUMK 16
#define CT   67
#define EPSL 1e-5f
#define TS   256
#define NT   (NN/TS)         // 144

// ---------------- scratch (static device globals; no allocation) ----------------
__device__ float g_P[BB*NN*CFI];        // [b][n][c]
__device__ float g_Q[BB*NN*CFI];        // [b][n][c]
__device__ float g_U[BB*NUMK*NN];
__device__ float g_Om[BB*NUMK*NN];

__device__ float g_WPQ[64*32];
__device__ float g_w1p[32], g_w1a[32], g_w1b[32], g_t1[32];
// packed f16x2 weights per layer: [k2][32] uint32 (single precision pass)
__device__ unsigned g_W2p[512];
__device__ unsigned g_W3p[512];
__device__ unsigned g_W4p[512];
__device__ float g_t2[32], g_t3[32], g_t4[32];
__device__ float g_wcA[32], g_wcB[32], g_wcC[32];
__device__ float g_bcv[3];
__device__ int   g_args64;

__device__ __forceinline__ float frcp(float x) { float y; asm("rcp.approx.f32 %0, %1;" : "=f"(y) : "f"(x)); return y; }
__device__ __forceinline__ float fex2(float x) { float y; asm("ex2.approx.f32 %0, %1;" : "=f"(y) : "f"(x)); return y; }

// m16n8k16 fp16 MMA, row.col, fp32 accumulate in-place
__device__ __forceinline__ void mma16(float* d, unsigned a0, unsigned a1, unsigned a2, unsigned a3,
                                      unsigned b0, unsigned b1) {
    asm volatile(
        "mma.sync.aligned.m16n8k16.row.col.f32.f16.f16.f32 "
        "{%0,%1,%2,%3}, {%4,%5,%6,%7}, {%8,%9}, {%0,%1,%2,%3};"
        : "+f"(d[0]), "+f"(d[1]), "+f"(d[2]), "+f"(d[3])
        : "r"(a0), "r"(a1), "r"(a2), "r"(a3), "r"(b0), "r"(b1));
}

// fast gelu: 0.5*(x + |x|*erf(|x|/sqrt2)), erf via A&S 7.1.25 3-term (|eps|<=2.5e-5)
__device__ __forceinline__ float gelu_f(float x) {
    float ax = fabsf(x);
    float z  = ax * 0.70710678118654752f;
    float t  = frcp(fmaf(z, 0.47047f, 1.0f));
    float e  = fex2(z * z * -1.4426950408889634f);
    float h  = fmaf(0.7478556f, t, -0.0958798f);
    h = fmaf(h, t, 0.3480242f);
    h = h * t;
    float E = fmaf(-h, e, 1.0f);          // erf(z), z >= 0
    return 0.5f * fmaf(ax, E, x);
}

// ---------------- kernel 1: fold BN, pack fp16 weights, detect args dtype ----------------
__global__ void prep_kernel(
    const float* __restrict__ W1, const float* __restrict__ g1, const float* __restrict__ b1,
    const float* __restrict__ m1, const float* __restrict__ v1,
    const float* __restrict__ W2, const float* __restrict__ g2, const float* __restrict__ b2,
    const float* __restrict__ m2, const float* __restrict__ v2,
    const float* __restrict__ W3, const float* __restrict__ g3, const float* __restrict__ b3,
    const float* __restrict__ m3, const float* __restrict__ v3,
    const float* __restrict__ W4, const float* __restrict__ g4, const float* __restrict__ b4,
    const float* __restrict__ m4, const float* __restrict__ v4,
    const float* __restrict__ Wc, const float* __restrict__ bc,
    const int*   __restrict__ args_i32)
{
    __shared__ float inv1[32], inv2[32], inv3[32], inv4[32];
    int t = threadIdx.x;
    if (t < 32) {
        float i1 = g1[t]*rsqrtf(v1[t]+EPSL); inv1[t]=i1; g_t1[t]=b1[t]-m1[t]*i1;
        float i2 = g2[t]*rsqrtf(v2[t]+EPSL); inv2[t]=i2; g_t2[t]=b2[t]-m2[t]*i2;
        float i3 = g3[t]*rsqrtf(v3[t]+EPSL); inv3[t]=i3; g_t3[t]=b3[t]-m3[t]*i3;
        float i4 = g4[t]*rsqrtf(v4[t]+EPSL); inv4[t]=i4; g_t4[t]=b4[t]-m4[t]*i4;
        g_wcA[t]=Wc[t]; g_wcB[t]=Wc[32+t]; g_wcC[t]=Wc[64+t];
        g_w1p[t]=W1[t*CT+64]*i1; g_w1a[t]=W1[t*CT+65]*i1; g_w1b[t]=W1[t*CT+66]*i1;
    }
    if (t < 3) g_bcv[t] = bc[t];
    if (t == 0) {
        int all_zero = 1;
        for (int i = 0; i < 128; i++) if (args_i32[2*i+1] != 0) { all_zero = 0; break; }
        g_args64 = all_zero;
    }
    __syncthreads();
    for (int idx = t; idx < 2048; idx += blockDim.x) {
        int r = idx >> 5, i = idx & 31;
        g_WPQ[idx] = (r < 32) ? W1[r*CT + i] * inv1[r]
                              : W1[(r-32)*CT + 32 + i] * inv1[r-32];
    }
    // packed fp16 weights: idx = k2*32 + n
    for (int idx = t; idx < 512; idx += blockDim.x) {
        int k2 = idx >> 5, n = idx & 31;
        __half2 p;
        p = __floats2half2_rn(W2[n*32 + 2*k2]*inv2[n], W2[n*32 + 2*k2 + 1]*inv2[n]);
        g_W2p[idx] = *(unsigned*)&p;
        p = __floats2half2_rn(W3[n*32 + 2*k2]*inv3[n], W3[n*32 + 2*k2 + 1]*inv3[n]);
        g_W3p[idx] = *(unsigned*)&p;
        p = __floats2half2_rn(W4[n*32 + 2*k2]*inv4[n], W4[n*32 + 2*k2 + 1]*inv4[n]);
        g_W4p[idx] = *(unsigned*)&p;
    }
}

// ---------------- kernel 2: P/Q = folded-W1 @ If, written [b][n][c] ----------------
__global__ void pq_kernel(const float* __restrict__ If)
{
    __shared__ float wf[2048];
    __shared__ float tb[256*33];
    int tid  = threadIdx.x;
    int b    = blockIdx.x / NT;
    int tile = blockIdx.x % NT;
    int n0   = tile * 256;

    for (int idx = tid; idx < 2048; idx += 256) wf[idx] = g_WPQ[idx];

    int n = n0 + tid;
    float x[32];
    #pragma unroll
    for (int i = 0; i < 32; i++) x[i] = If[((size_t)b*32 + i)*NN + n];
    __syncthreads();

    size_t base = ((size_t)b*NN + n0) * 32;

    #pragma unroll
    for (int c = 0; c < 32; c++) {
        float acc = 0.f;
        #pragma unroll
        for (int i = 0; i < 32; i += 4) {
            float4 w = *(const float4*)&wf[c*32 + i];
            acc += w.x*x[i] + w.y*x[i+1] + w.z*x[i+2] + w.w*x[i+3];
        }
        tb[tid*33 + c] = acc;
    }
    __syncthreads();
    for (int idx = tid; idx < 8192; idx += 256)
        g_P[base + idx] = tb[(idx >> 5)*33 + (idx & 31)];
    __syncthreads();

    #pragma unroll
    for (int c = 0; c < 32; c++) {
        float acc = 0.f;
        #pragma unroll
        for (int i = 0; i < 32; i += 4) {
            float4 w = *(const float4*)&wf[(32+c)*32 + i];
            acc += w.x*x[i] + w.y*x[i+1] + w.z*x[i+2] + w.w*x[i+3];
        }
        tb[tid*33 + c] = acc;
    }
    __syncthreads();
    for (int idx = tid; idx < 8192; idx += 256)
        g_Q[base + idx] = tb[(idx >> 5)*33 + (idx & 31)];
}

// ---------------- register-resident MLP layer (single-pass fp16 mma) ----------------
// x layout: x[mt*16 + nt*4 + e], channel = 8*nt + 2*tg + (e&1),
//           sample row = 32*warp + 16*mt + g + 8*(e>>1)
template<bool ADD>
__device__ __forceinline__ void layer_reg(
    const float* xin, float* xout,
    const unsigned* __restrict__ wp, const float* __restrict__ bias,
    const float* resid, int g, int tg)
{
    // pack activations to fp16
    unsigned ah[16];
    #pragma unroll
    for (int mt = 0; mt < 2; mt++)
    #pragma unroll
    for (int nt = 0; nt < 4; nt++) {
        int base = mt*16 + nt*4;
        #pragma unroll
        for (int hh = 0; hh < 2; hh++) {
            __half2 p = __floats2half2_rn(xin[base + 2*hh], xin[base + 2*hh + 1]);
            ah[(mt*4 + nt)*2 + hh] = *(unsigned*)&p;
        }
    }
    // init accumulators with bias
    float d[32];
    #pragma unroll
    for (int nt = 0; nt < 4; nt++) {
        float2 bv = __ldg((const float2*)bias + 4*nt + tg);
        #pragma unroll
        for (int mt = 0; mt < 2; mt++) {
            d[mt*16 + nt*4 + 0] = bv.x; d[mt*16 + nt*4 + 1] = bv.y;
            d[mt*16 + nt*4 + 2] = bv.x; d[mt*16 + nt*4 + 3] = bv.y;
        }
    }
    // mma mainloop: 2 k-steps x 4 n-tiles x 2 m-tiles, single pass
    #pragma unroll
    for (int ks = 0; ks < 2; ks++) {
        #pragma unroll
        for (int nt = 0; nt < 4; nt++) {
            unsigned b0 = __ldg(wp + (ks*8 + tg    )*32 + 8*nt + g);
            unsigned b1 = __ldg(wp + (ks*8 + tg + 4)*32 + 8*nt + g);
            #pragma unroll
            for (int mt = 0; mt < 2; mt++) {
                int ia  = (mt*4 + 2*ks    )*2;
                int ia2 = (mt*4 + 2*ks + 1)*2;
                mma16(d + mt*16 + nt*4, ah[ia], ah[ia+1], ah[ia2], ah[ia2+1], b0, b1);
            }
        }
    }
    #pragma unroll
    for (int i = 0; i < 32; i++) {
        float v = d[i];
        if (ADD) v += resid[i];
        xout[i] = gelu_f(v);
    }
}

// ---------------- kernel 3: main fused MLP, fully register-resident ----------------
__global__ void __launch_bounds__(256) main_kernel(
    const float* __restrict__ Pf,
    const float* __restrict__ Of,
    const void*  __restrict__ args)
{
    int bk   = blockIdx.x / NT;
    int tile = blockIdx.x % NT;
    int b = bk / NUMK, k = bk % NUMK;
    int n0 = tile * TS;
    int tid = threadIdx.x;
    int w = tid >> 5, lane = tid & 31;
    int g = lane >> 2, tg = lane & 3;

    float xa[32], xb[32];
    float pfs[4];

    // stage 1: h1 in D-frag register layout
    {
        float2 w1p2[4], w1a2[4], w1b2[4], t12[4];
        #pragma unroll
        for (int q = 0; q < 4; q++) {
            w1p2[q] = __ldg((const float2*)g_w1p + 4*q + tg);
            w1a2[q] = __ldg((const float2*)g_w1a + 4*q + tg);
            w1b2[q] = __ldg((const float2*)g_w1b + 4*q + tg);
            t12[q]  = __ldg((const float2*)g_t1  + 4*q + tg);
        }
        const float* of0p = Of + ((size_t)(b*2+0)*NUMK + k)*NN;
        const float* of1p = Of + ((size_t)(b*2+1)*NUMK + k)*NN;
        int use64 = g_args64;
        #pragma unroll
        for (int mt = 0; mt < 2; mt++)
        #pragma unroll
        for (int hh = 0; hh < 2; hh++) {
            int s = 32*w + 16*mt + 8*hh + g;
            int n = n0 + s;
            size_t ai = ((size_t)(b*NUMK + k))*NN + n;
            int j;
            if (use64) j = (int)__ldg((const long long*)args + ai);
            else       j = __ldg((const int*)args + ai);
            float pf = __ldg(Pf + (size_t)b*NN + j);
            pfs[mt*2 + hh] = pf;
            float o0 = __ldg(of0p + n);
            float o1 = __ldg(of1p + n);
            const float2* P2 = (const float2*)g_P + (size_t)(b*NN + n)*16 + tg;
            const float2* Q2 = (const float2*)g_Q + (size_t)(b*NN + j)*16 + tg;
            #pragma unroll
            for (int q = 0; q < 4; q++) {
                float2 p  = __ldg(P2 + 4*q);
                float2 qv = __ldg(Q2 + 4*q);
                float z0 = p.x + qv.x + w1p2[q].x*pf + w1a2[q].x*o0 + w1b2[q].x*o1 + t12[q].x;
                float z1 = p.y + qv.y + w1p2[q].y*pf + w1a2[q].y*o0 + w1b2[q].y*o1 + t12[q].y;
                xa[mt*16 + q*4 + 2*hh]     = gelu_f(z0);
                xa[mt*16 + q*4 + 2*hh + 1] = gelu_f(z1);
            }
        }
    }

    layer_reg<false>(xa, xb, g_W2p, g_t2, nullptr, g, tg);   // h2 = xb
    layer_reg<false>(xb, xa, g_W3p, g_t3, nullptr, g, tg);   // l3 = xa
    layer_reg<true >(xa, xa, g_W4p, g_t4, xb,      g, tg);   // XF = gelu(h2 + bn4(W4 l3))

    // head: 3x32 dot per sample, reduce across the 4 tg-lanes of each sample
    {
        float2 wA2[4], wB2[4], wC2[4];
        #pragma unroll
        for (int nt = 0; nt < 4; nt++) {
            wA2[nt] = __ldg((const float2*)g_wcA + 4*nt + tg);
            wB2[nt] = __ldg((const float2*)g_wcB + 4*nt + tg);
            wC2[nt] = __ldg((const float2*)g_wcC + 4*nt + tg);
        }
        float bc0 = g_bcv[0], bc1 = g_bcv[1], bc2 = g_bcv[2];
        size_t obase = ((size_t)(b*NUMK + k))*NN + n0;
        #pragma unroll
        for (int mt = 0; mt < 2; mt++)
        #pragma unroll
        for (int hh = 0; hh < 2; hh++) {
            float a = 0.f, be = 0.f, om = 0.f;
            #pragma unroll
            for (int nt = 0; nt < 4; nt++) {
                float x0 = xa[mt*16 + nt*4 + 2*hh];
                float x1 = xa[mt*16 + nt*4 + 2*hh + 1];
                a  += wA2[nt].x*x0 + wA2[nt].y*x1;
                be += wB2[nt].x*x0 + wB2[nt].y*x1;
                om += wC2[nt].x*x0 + wC2[nt].y*x1;
            }
            a  += __shfl_xor_sync(0xffffffffu, a, 1);
            a  += __shfl_xor_sync(0xffffffffu, a, 2);
            be += __shfl_xor_sync(0xffffffffu, be, 1);
            be += __shfl_xor_sync(0xffffffffu, be, 2);
            om += __shfl_xor_sync(0xffffffffu, om, 1);
            om += __shfl_xor_sync(0xffffffffu, om, 2);
            if (tg == 0) {
                int s = 32*w + 16*mt + 8*hh + g;
                float U = (a + bc0 + 1.0f)*pfs[mt*2 + hh] + (be + bc1);
                g_U[obase + s]  = U;
                g_Om[obase + s] = om + bc2;
            }
        }
    }
}

// ---------------- kernel 4: softmax over NUM + weighted sum ----------------
__global__ void epi_kernel(float* __restrict__ out)
{
    int gid = blockIdx.x * blockDim.x + threadIdx.x;
    if (gid >= BB*NN) return;
    int b = gid / NN, n = gid % NN;
    size_t base = (size_t)b*NUMK*NN + n;
    float om[NUMK];
    float m = -3.4e38f;
    #pragma unroll
    for (int k = 0; k < NUMK; k++) {
        om[k] = g_Om[base + (size_t)k*NN];
        m = fmaxf(m, om[k]);
    }
    float num = 0.f, den = 0.f;
    #pragma unroll
    for (int k = 0; k < NUMK; k++) {
        float e = fex2((om[k] - m) * 1.4426950408889634f);
        den += e;
        num += e * g_U[base + (size_t)k*NN];
    }
    out[gid] = num * frcp(den);
}

// ---------------- launch ----------------
extern "C" void kernel_launch(void* const* d_in, const int* in_sizes, int n_in,
                              void* d_out, int out_size)
{
    const float* If = (const float*)d_in[0];
    const float* Pf = (const float*)d_in[1];
    const float* Of = (const float*)d_in[2];
    const void*  args = d_in[3];
    const float* W1 = (const float*)d_in[4];
    const float* g1 = (const float*)d_in[5];
    const float* b1 = (const float*)d_in[6];
    const float* m1 = (const float*)d_in[7];
    const float* v1 = (const float*)d_in[8];
    const float* W2 = (const float*)d_in[9];
    const float* g2 = (const float*)d_in[10];
    const float* b2 = (const float*)d_in[11];
    const float* m2 = (const float*)d_in[12];
    const float* v2 = (const float*)d_in[13];
    const float* W3 = (const float*)d_in[14];
    const float* g3 = (const float*)d_in[15];
    const float* b3 = (const float*)d_in[16];
    const float* m3 = (const float*)d_in[17];
    const float* v3 = (const float*)d_in[18];
    const float* W4 = (const float*)d_in[19];
    const float* g4 = (const float*)d_in[20];
    const float* b4 = (const float*)d_in[21];
    const float* m4 = (const float*)d_in[22];
    const float* v4 = (const float*)d_in[23];
    const float* Wc = (const float*)d_in[24];
    const float* bc = (const float*)d_in[25];

    prep_kernel<<<1, 256>>>(W1, g1, b1, m1, v1,
                            W2, g2, b2, m2, v2,
                            W3, g3, b3, m3, v3,
                            W4, g4, b4, m4, v4,
                            Wc, bc, (const int*)args);

    pq_kernel<<<BB*NT, 256>>>(If);

    main_kernel<<<BB*NUMK*NT, 256>>>(Pf, Of, args);

    epi_kernel<<<(BB*NN + 255)/256, 256>>>((float*)d_out);
}

// round 10
// speedup vs baseline: 1.6993x; 1.0767x over previous
#include <cuda_runtime.h>
#include <cuda_fp16.h>
#include <cstdint>

#define BB   2
#define CFI  32
#define HH   192
#define WWD  192
#define NN   (HH*WWD)        // 36864
#define NUMK 16
#define CT   67
#define EPSL 1e-5f
#define TS   256
#define NT   (NN/TS)         // 144

// ---------------- scratch (static device globals; no allocation) ----------------
__device__ float g_P[BB*NN*CFI];        // [b][n][c]
__device__ float g_Q[BB*NN*CFI];        // [b][n][c]
__device__ float g_U[BB*NUMK*NN];
__device__ float g_Om[BB*NUMK*NN];

__device__ float g_WPQ[64*32];
__device__ float g_w1p[32], g_w1a[32], g_w1b[32], g_t1[32];
// packed f16x2 weights per layer: [k2][32] uint32 (single precision pass)
__device__ unsigned g_W2p[512];
__device__ unsigned g_W3p[512];
__device__ unsigned g_W4p[512];
__device__ float g_t2[32], g_t3[32], g_t4[32];
__device__ float g_wcA[32], g_wcB[32], g_wcC[32];
__device__ float g_bcv[3];
__device__ int   g_args64;

__device__ __forceinline__ float frcp(float x) { float y; asm("rcp.approx.f32 %0, %1;" : "=f"(y) : "f"(x)); return y; }
__device__ __forceinline__ float fex2(float x) { float y; asm("ex2.approx.f32 %0, %1;" : "=f"(y) : "f"(x)); return y; }

// ---------------- packed f32x2 helpers ----------------
__device__ __forceinline__ float2 fma2(float2 a, float2 b, float2 c) {
    float2 r;
    asm("fma.rn.f32x2 %0, %1, %2, %3;"
        : "=l"(*(unsigned long long*)&r)
        : "l"(*(const unsigned long long*)&a),
          "l"(*(const unsigned long long*)&b),
          "l"(*(const unsigned long long*)&c));
    return r;
}
__device__ __forceinline__ float2 mul2(float2 a, float2 b) {
    float2 r;
    asm("mul.rn.f32x2 %0, %1, %2;"
        : "=l"(*(unsigned long long*)&r)
        : "l"(*(const unsigned long long*)&a),
          "l"(*(const unsigned long long*)&b));
    return r;
}
__device__ __forceinline__ float2 add2(float2 a, float2 b) {
    float2 r;
    asm("add.rn.f32x2 %0, %1, %2;"
        : "=l"(*(unsigned long long*)&r)
        : "l"(*(const unsigned long long*)&a),
          "l"(*(const unsigned long long*)&b));
    return r;
}
__device__ __forceinline__ float2 d2(float v) { return make_float2(v, v); }

// packed fast gelu: 0.5*(x + |x|*erf(|x|/sqrt2)), erf via A&S 7.1.25 3-term (|eps|<=2.5e-5)
// identical rounding to the scalar path (all ops .rn)
__device__ __forceinline__ float2 gelu2(float2 x) {
    float2 ax = make_float2(fabsf(x.x), fabsf(x.y));   // alu pipe
    float2 z  = mul2(ax, d2(0.70710678118654752f));
    float2 q  = fma2(z, d2(0.47047f), d2(1.0f));
    float2 t; t.x = frcp(q.x); t.y = frcp(q.y);        // MUFU
    float2 s  = mul2(mul2(z, z), d2(-1.4426950408889634f));
    float2 e; e.x = fex2(s.x); e.y = fex2(s.y);        // MUFU
    float2 h  = fma2(d2(0.7478556f), t, d2(-0.0958798f));
    h = fma2(h, t, d2(0.3480242f));
    h = mul2(h, t);
    float2 he = mul2(h, e);
    float2 E  = fma2(he, d2(-1.0f), d2(1.0f));         // erf(z), z >= 0
    float2 w  = mul2(ax, E);
    return mul2(add2(x, w), d2(0.5f));
}

// scalar version (used only in pq/epi-free spots if needed)
__device__ __forceinline__ float gelu_f(float x) {
    float2 r = gelu2(make_float2(x, x));
    return r.x;
}

// m16n8k16 fp16 MMA, row.col, fp32 accumulate in-place
__device__ __forceinline__ void mma16(float* d, unsigned a0, unsigned a1, unsigned a2, unsigned a3,
                                      unsigned b0, unsigned b1) {
    asm volatile(
        "mma.sync.aligned.m16n8k16.row.col.f32.f16.f16.f32 "
        "{%0,%1,%2,%3}, {%4,%5,%6,%7}, {%8,%9}, {%0,%1,%2,%3};"
        : "+f"(d[0]), "+f"(d[1]), "+f"(d[2]), "+f"(d[3])
        : "r"(a0), "r"(a1), "r"(a2), "r"(a3), "r"(b0), "r"(b1));
}

// ---------------- kernel 1: fold BN, pack fp16 weights, detect args dtype ----------------
__global__ void prep_kernel(
    const float* __restrict__ W1, const float* __restrict__ g1, const float* __restrict__ b1,
    const float* __restrict__ m1, const float* __restrict__ v1,
    const float* __restrict__ W2, const float* __restrict__ g2, const float* __restrict__ b2,
    const float* __restrict__ m2, const float* __restrict__ v2,
    const float* __restrict__ W3, const float* __restrict__ g3, const float* __restrict__ b3,
    const float* __restrict__ m3, const float* __restrict__ v3,
    const float* __restrict__ W4, const float* __restrict__ g4, const float* __restrict__ b4,
    const float* __restrict__ m4, const float* __restrict__ v4,
    const float* __restrict__ Wc, const float* __restrict__ bc,
    const int*   __restrict__ args_i32)
{
    __shared__ float inv1[32], inv2[32], inv3[32], inv4[32];
    int t = threadIdx.x;
    if (t < 32) {
        float i1 = g1[t]*rsqrtf(v1[t]+EPSL); inv1[t]=i1; g_t1[t]=b1[t]-m1[t]*i1;
        float i2 = g2[t]*rsqrtf(v2[t]+EPSL); inv2[t]=i2; g_t2[t]=b2[t]-m2[t]*i2;
        float i3 = g3[t]*rsqrtf(v3[t]+EPSL); inv3[t]=i3; g_t3[t]=b3[t]-m3[t]*i3;
        float i4 = g4[t]*rsqrtf(v4[t]+EPSL); inv4[t]=i4; g_t4[t]=b4[t]-m4[t]*i4;
        g_wcA[t]=Wc[t]; g_wcB[t]=Wc[32+t]; g_wcC[t]=Wc[64+t];
        g_w1p[t]=W1[t*CT+64]*i1; g_w1a[t]=W1[t*CT+65]*i1; g_w1b[t]=W1[t*CT+66]*i1;
    }
    if (t < 3) g_bcv[t] = bc[t];
    if (t == 0) {
        int all_zero = 1;
        for (int i = 0; i < 128; i++) if (args_i32[2*i+1] != 0) { all_zero = 0; break; }
        g_args64 = all_zero;
    }
    __syncthreads();
    for (int idx = t; idx < 2048; idx += blockDim.x) {
        int r = idx >> 5, i = idx & 31;
        g_WPQ[idx] = (r < 32) ? W1[r*CT + i] * inv1[r]
                              : W1[(r-32)*CT + 32 + i] * inv1[r-32];
    }
    // packed fp16 weights: idx = k2*32 + n
    for (int idx = t; idx < 512; idx += blockDim.x) {
        int k2 = idx >> 5, n = idx & 31;
        __half2 p;
        p = __floats2half2_rn(W2[n*32 + 2*k2]*inv2[n], W2[n*32 + 2*k2 + 1]*inv2[n]);
        g_W2p[idx] = *(unsigned*)&p;
        p = __floats2half2_rn(W3[n*32 + 2*k2]*inv3[n], W3[n*32 + 2*k2 + 1]*inv3[n]);
        g_W3p[idx] = *(unsigned*)&p;
        p = __floats2half2_rn(W4[n*32 + 2*k2]*inv4[n], W4[n*32 + 2*k2 + 1]*inv4[n]);
        g_W4p[idx] = *(unsigned*)&p;
    }
}

// ---------------- kernel 2: P/Q = folded-W1 @ If, written [b][n][c] ----------------
__global__ void pq_kernel(const float* __restrict__ If)
{
    __shared__ float wf[2048];
    __shared__ float tb[256*33];
    int tid  = threadIdx.x;
    int b    = blockIdx.x / NT;
    int tile = blockIdx.x % NT;
    int n0   = tile * 256;

    for (int idx = tid; idx < 2048; idx += 256) wf[idx] = g_WPQ[idx];

    int n = n0 + tid;
    float x[32];
    #pragma unroll
    for (int i = 0; i < 32; i++) x[i] = If[((size_t)b*32 + i)*NN + n];
    __syncthreads();

    size_t base = ((size_t)b*NN + n0) * 32;

    #pragma unroll
    for (int c = 0; c < 32; c++) {
        float acc = 0.f;
        #pragma unroll
        for (int i = 0; i < 32; i += 4) {
            float4 w = *(const float4*)&wf[c*32 + i];
            acc += w.x*x[i] + w.y*x[i+1] + w.z*x[i+2] + w.w*x[i+3];
        }
        tb[tid*33 + c] = acc;
    }
    __syncthreads();
    for (int idx = tid; idx < 8192; idx += 256)
        g_P[base + idx] = tb[(idx >> 5)*33 + (idx & 31)];
    __syncthreads();

    #pragma unroll
    for (int c = 0; c < 32; c++) {
        float acc = 0.f;
        #pragma unroll
        for (int i = 0; i < 32; i += 4) {
            float4 w = *(const float4*)&wf[(32+c)*32 + i];
            acc += w.x*x[i] + w.y*x[i+1] + w.z*x[i+2] + w.w*x[i+3];
        }
        tb[tid*33 + c] = acc;
    }
    __syncthreads();
    for (int idx = tid; idx < 8192; idx += 256)
        g_Q[base + idx] = tb[(idx >> 5)*33 + (idx & 31)];
}

// ---------------- register-resident MLP layer (single-pass fp16 mma) ----------------
// x layout: x[mt*16 + nt*4 + e], channel = 8*nt + 2*tg + (e&1),
//           sample row = 32*warp + 16*mt + g + 8*(e>>1)
template<bool ADD>
__device__ __forceinline__ void layer_reg(
    const float* xin, float* xout,
    const unsigned* __restrict__ wp, const float* __restrict__ bias,
    const float* resid, int g, int tg)
{
    // pack activations to fp16
    unsigned ah[16];
    #pragma unroll
    for (int mt = 0; mt < 2; mt++)
    #pragma unroll
    for (int nt = 0; nt < 4; nt++) {
        int base = mt*16 + nt*4;
        #pragma unroll
        for (int hh = 0; hh < 2; hh++) {
            __half2 p = __floats2half2_rn(xin[base + 2*hh], xin[base + 2*hh + 1]);
            ah[(mt*4 + nt)*2 + hh] = *(unsigned*)&p;
        }
    }
    // init accumulators with bias
    float d[32];
    #pragma unroll
    for (int nt = 0; nt < 4; nt++) {
        float2 bv = __ldg((const float2*)bias + 4*nt + tg);
        #pragma unroll
        for (int mt = 0; mt < 2; mt++) {
            d[mt*16 + nt*4 + 0] = bv.x; d[mt*16 + nt*4 + 1] = bv.y;
            d[mt*16 + nt*4 + 2] = bv.x; d[mt*16 + nt*4 + 3] = bv.y;
        }
    }
    // mma mainloop: 2 k-steps x 4 n-tiles x 2 m-tiles, single pass
    #pragma unroll
    for (int ks = 0; ks < 2; ks++) {
        #pragma unroll
        for (int nt = 0; nt < 4; nt++) {
            unsigned b0 = __ldg(wp + (ks*8 + tg    )*32 + 8*nt + g);
            unsigned b1 = __ldg(wp + (ks*8 + tg + 4)*32 + 8*nt + g);
            #pragma unroll
            for (int mt = 0; mt < 2; mt++) {
                int ia  = (mt*4 + 2*ks    )*2;
                int ia2 = (mt*4 + 2*ks + 1)*2;
                mma16(d + mt*16 + nt*4, ah[ia], ah[ia+1], ah[ia2], ah[ia2+1], b0, b1);
            }
        }
    }
    // packed-pair gelu epilogue (pairs = adjacent channels, natural D-frag pairs)
    #pragma unroll
    for (int i = 0; i < 32; i += 2) {
        float2 v = make_float2(d[i], d[i+1]);
        if (ADD) v = add2(v, make_float2(resid[i], resid[i+1]));
        float2 r = gelu2(v);
        xout[i] = r.x; xout[i+1] = r.y;
    }
}

// ---------------- kernel 3: main fused MLP, fully register-resident ----------------
__global__ void __launch_bounds__(256) main_kernel(
    const float* __restrict__ Pf,
    const float* __restrict__ Of,
    const void*  __restrict__ args)
{
    int bk   = blockIdx.x / NT;
    int tile = blockIdx.x % NT;
    int b = bk / NUMK, k = bk % NUMK;
    int n0 = tile * TS;
    int tid = threadIdx.x;
    int w = tid >> 5, lane = tid & 31;
    int g = lane >> 2, tg = lane & 3;

    float xa[32], xb[32];
    float pfs[4];

    // stage 1: h1 in D-frag register layout
    {
        float2 w1p2[4], w1a2[4], w1b2[4], t12[4];
        #pragma unroll
        for (int q = 0; q < 4; q++) {
            w1p2[q] = __ldg((const float2*)g_w1p + 4*q + tg);
            w1a2[q] = __ldg((const float2*)g_w1a + 4*q + tg);
            w1b2[q] = __ldg((const float2*)g_w1b + 4*q + tg);
            t12[q]  = __ldg((const float2*)g_t1  + 4*q + tg);
        }
        const float* of0p = Of + ((size_t)(b*2+0)*NUMK + k)*NN;
        const float* of1p = Of + ((size_t)(b*2+1)*NUMK + k)*NN;
        int use64 = g_args64;
        #pragma unroll
        for (int mt = 0; mt < 2; mt++)
        #pragma unroll
        for (int hh = 0; hh < 2; hh++) {
            int s = 32*w + 16*mt + 8*hh + g;
            int n = n0 + s;
            size_t ai = ((size_t)(b*NUMK + k))*NN + n;
            int j;
            if (use64) j = (int)__ldg((const long long*)args + ai);
            else       j = __ldg((const int*)args + ai);
            float pf = __ldg(Pf + (size_t)b*NN + j);
            pfs[mt*2 + hh] = pf;
            float o0 = __ldg(of0p + n);
            float o1 = __ldg(of1p + n);
            const float2* P2 = (const float2*)g_P + (size_t)(b*NN + n)*16 + tg;
            const float2* Q2 = (const float2*)g_Q + (size_t)(b*NN + j)*16 + tg;
            #pragma unroll
            for (int q = 0; q < 4; q++) {
                float2 p  = __ldg(P2 + 4*q);
                float2 qv = __ldg(Q2 + 4*q);
                float z0 = p.x + qv.x + w1p2[q].x*pf + w1a2[q].x*o0 + w1b2[q].x*o1 + t12[q].x;
                float z1 = p.y + qv.y + w1p2[q].y*pf + w1a2[q].y*o0 + w1b2[q].y*o1 + t12[q].y;
                float2 r = gelu2(make_float2(z0, z1));
                xa[mt*16 + q*4 + 2*hh]     = r.x;
                xa[mt*16 + q*4 + 2*hh + 1] = r.y;
            }
        }
    }

    layer_reg<false>(xa, xb, g_W2p, g_t2, nullptr, g, tg);   // h2 = xb
    layer_reg<false>(xb, xa, g_W3p, g_t3, nullptr, g, tg);   // l3 = xa
    layer_reg<true >(xa, xa, g_W4p, g_t4, xb,      g, tg);   // XF = gelu(h2 + bn4(W4 l3))

    // head: 3x32 dot per sample, reduce across the 4 tg-lanes of each sample
    {
        float2 wA2[4], wB2[4], wC2[4];
        #pragma unroll
        for (int nt = 0; nt < 4; nt++) {
            wA2[nt] = __ldg((const float2*)g_wcA + 4*nt + tg);
            wB2[nt] = __ldg((const float2*)g_wcB + 4*nt + tg);
            wC2[nt] = __ldg((const float2*)g_wcC + 4*nt + tg);
        }
        float bc0 = g_bcv[0], bc1 = g_bcv[1], bc2 = g_bcv[2];
        size_t obase = ((size_t)(b*NUMK + k))*NN + n0;
        #pragma unroll
        for (int mt = 0; mt < 2; mt++)
        #pragma unroll
        for (int hh = 0; hh < 2; hh++) {
            float a = 0.f, be = 0.f, om = 0.f;
            #pragma unroll
            for (int nt = 0; nt < 4; nt++) {
                float x0 = xa[mt*16 + nt*4 + 2*hh];
                float x1 = xa[mt*16 + nt*4 + 2*hh + 1];
                a  += wA2[nt].x*x0 + wA2[nt].y*x1;
                be += wB2[nt].x*x0 + wB2[nt].y*x1;
                om += wC2[nt].x*x0 + wC2[nt].y*x1;
            }
            a  += __shfl_xor_sync(0xffffffffu, a, 1);
            a  += __shfl_xor_sync(0xffffffffu, a, 2);
            be += __shfl_xor_sync(0xffffffffu, be, 1);
            be += __shfl_xor_sync(0xffffffffu, be, 2);
            om += __shfl_xor_sync(0xffffffffu, om, 1);
            om += __shfl_xor_sync(0xffffffffu, om, 2);
            if (tg == 0) {
                int s = 32*w + 16*mt + 8*hh + g;
                float U = (a + bc0 + 1.0f)*pfs[mt*2 + hh] + (be + bc1);
                g_U[obase + s]  = U;
                g_Om[obase + s] = om + bc2;
            }
        }
    }
}

// ---------------- kernel 4: softmax over NUM + weighted sum ----------------
__global__ void epi_kernel(float* __restrict__ out)
{
    int gid = blockIdx.x * blockDim.x + threadIdx.x;
    if (gid >= BB*NN) return;
    int b = gid / NN, n = gid % NN;
    size_t base = (size_t)b*NUMK*NN + n;
    float om[NUMK];
    float m = -3.4e38f;
    #pragma unroll
    for (int k = 0; k < NUMK; k++) {
        om[k] = g_Om[base + (size_t)k*NN];
        m = fmaxf(m, om[k]);
    }
    float num = 0.f, den = 0.f;
    #pragma unroll
    for (int k = 0; k < NUMK; k++) {
        float e = fex2((om[k] - m) * 1.4426950408889634f);
        den += e;
        num += e * g_U[base + (size_t)k*NN];
    }
    out[gid] = num * frcp(den);
}

// ---------------- launch ----------------
extern "C" void kernel_launch(void* const* d_in, const int* in_sizes, int n_in,
                              void* d_out, int out_size)
{
    const float* If = (const float*)d_in[0];
    const float* Pf = (const float*)d_in[1];
    const float* Of = (const float*)d_in[2];
    const void*  args = d_in[3];
    const float* W1 = (const float*)d_in[4];
    const float* g1 = (const float*)d_in[5];
    const float* b1 = (const float*)d_in[6];
    const float* m1 = (const float*)d_in[7];
    const float* v1 = (const float*)d_in[8];
    const float* W2 = (const float*)d_in[9];
    const float* g2 = (const float*)d_in[10];
    const float* b2 = (const float*)d_in[11];
    const float* m2 = (const float*)d_in[12];
    const float* v2 = (const float*)d_in[13];
    const float* W3 = (const float*)d_in[14];
    const float* g3 = (const float*)d_in[15];
    const float* b3 = (const float*)d_in[16];
    const float* m3 = (const float*)d_in[17];
    const float* v3 = (const float*)d_in[18];
    const float* W4 = (const float*)d_in[19];
    const float* g4 = (const float*)d_in[20];
    const float* b4 = (const float*)d_in[21];
    const float* m4 = (const float*)d_in[22];
    const float* v4 = (const float*)d_in[23];
    const float* Wc = (const float*)d_in[24];
    const float* bc = (const float*)d_in[25];

    prep_kernel<<<1, 256>>>(W1, g1, b1, m1, v1,
                            W2, g2, b2, m2, v2,
                            W3, g3, b3, m3, v3,
                            W4, g4, b4, m4, v4,
                            Wc, bc, (const int*)args);

    pq_kernel<<<BB*NT, 256>>>(If);

    main_kernel<<<BB*NUMK*NT, 256>>>(Pf, Of, args);

    epi_kernel<<<(BB*NN + 255)/256, 256>>>((float*)d_out);
}